// round 14
// baseline (speedup 1.0000x reference)
#include <cuda_runtime.h>
#include <cuda_bf16.h>
#include <cstdint>
#include <cstddef>

#define EPS_VAL 0.5f
typedef unsigned long long u64;
typedef unsigned int u32;

// ===================== helpers =====================
__device__ __forceinline__ u64 ffma2(u64 a, u64 b, u64 c) {
    u64 d;
    asm("fma.rn.f32x2 %0, %1, %2, %3;" : "=l"(d) : "l"(a), "l"(b), "l"(c));
    return d;
}
__device__ __forceinline__ float f2sum(u64 v) {
    return __uint_as_float((unsigned)(v & 0xffffffffu)) +
           __uint_as_float((unsigned)(v >> 32));
}
__device__ __forceinline__ void mma_bf16(float* d, const u32* a, u32 b0, u32 b1) {
    asm volatile(
        "mma.sync.aligned.m16n8k16.row.col.f32.bf16.bf16.f32 "
        "{%0,%1,%2,%3}, {%4,%5,%6,%7}, {%8,%9}, {%0,%1,%2,%3};"
        : "+f"(d[0]), "+f"(d[1]), "+f"(d[2]), "+f"(d[3])
        : "r"(a[0]), "r"(a[1]), "r"(a[2]), "r"(a[3]), "r"(b0), "r"(b1));
}
__device__ __forceinline__ void ldmx4(u32* r, u32 addr) {
    asm volatile("ldmatrix.sync.aligned.m8n8.x4.shared.b16 {%0,%1,%2,%3}, [%4];"
        : "=r"(r[0]), "=r"(r[1]), "=r"(r[2]), "=r"(r[3]) : "r"(addr));
}
__device__ __forceinline__ u32 smem_u32(const void* p) {
    u32 a;
    asm("{ .reg .u64 t; cvta.to.shared.u64 t, %1; cvt.u32.u64 %0, t; }"
        : "=r"(a) : "l"(p));
    return a;
}
__device__ __forceinline__ u32 pack_bf16x2(__nv_bfloat16 lo, __nv_bfloat16 hi) {
    return (u32)__bfloat16_as_ushort(lo) | ((u32)__bfloat16_as_ushort(hi) << 16);
}
#define BAR_SYNC(id)   asm volatile("bar.sync %0, 512;"   :: "r"(id) : "memory")
#define BAR_ARRIVE(id) asm volatile("bar.arrive %0, 512;" :: "r"(id) : "memory")

// Scratch: node projections y [N_MAX, 256] fp32
#define N_MAX 100000
__device__ float g_y[(size_t)N_MAX * 256];

// ---------------------------------------------------------------------------
// Kernel 1: y = x @ W1^T + 0.5*b1  (SIMT fp32 f32x2 — exact; unchanged)
// ---------------------------------------------------------------------------
__global__ __launch_bounds__(256) void node_proj_kernel(
    const float* __restrict__ x, const float* __restrict__ W1,
    const float* __restrict__ b1, int N)
{
    extern __shared__ __align__(16) float sm[];
    float* xs = sm;
    float* ws = sm + 64 * 132;
    float* __restrict__ y = g_y;

    const int tid = threadIdx.x;
    const int n0 = blockIdx.x * 64;
    const int j0 = blockIdx.y * 64;

    #pragma unroll
    for (int it = 0; it < 8; it++) {
        int idx = tid + it * 256;
        int r = idx >> 5, c = (idx & 31) << 2;
        int gr = n0 + r;
        float4 v = make_float4(0.f, 0.f, 0.f, 0.f);
        if (gr < N) v = *(const float4*)(x + (size_t)gr * 128 + c);
        *(float4*)(xs + r * 132 + c) = v;
    }
    #pragma unroll
    for (int it = 0; it < 8; it++) {
        int idx = tid + it * 256;
        int r = idx >> 5, c = (idx & 31) << 2;
        float4 v = *(const float4*)(W1 + (size_t)(j0 + r) * 128 + c);
        *(float4*)(ws + r * 132 + c) = v;
    }
    __syncthreads();

    const int l = tid & 31, w = tid >> 5;
    const int le = l >> 3, lo = l & 7;
    const int we = w & 3,  wo = w >> 2;

    u64 acc[4][4];
    #pragma unroll
    for (int i = 0; i < 4; i++)
        #pragma unroll
        for (int r = 0; r < 4; r++) acc[i][r] = 0ull;

    const float* xbase = xs + (16 * we + le) * 132;
    const float* wbase = ws + (32 * wo + lo) * 132;

    #pragma unroll 2
    for (int k = 0; k < 128; k += 4) {
        ulonglong2 xa[4], wb[4];
        #pragma unroll
        for (int i = 0; i < 4; i++) xa[i] = *(const ulonglong2*)(xbase + (4 * i) * 132 + k);
        #pragma unroll
        for (int r = 0; r < 4; r++) wb[r] = *(const ulonglong2*)(wbase + (8 * r) * 132 + k);
        #pragma unroll
        for (int i = 0; i < 4; i++)
            #pragma unroll
            for (int r = 0; r < 4; r++) {
                acc[i][r] = ffma2(xa[i].x, wb[r].x, acc[i][r]);
                acc[i][r] = ffma2(xa[i].y, wb[r].y, acc[i][r]);
            }
    }
    __syncthreads();

    float* stage = sm;
    #pragma unroll
    for (int i = 0; i < 4; i++)
        #pragma unroll
        for (int r = 0; r < 4; r++) {
            int rl = 16 * we + le + 4 * i;
            int cl = 32 * wo + lo + 8 * r;
            stage[rl * 68 + cl] = f2sum(acc[i][r]) + 0.5f * b1[j0 + cl];
        }
    __syncthreads();

    #pragma unroll
    for (int it = 0; it < 4; it++) {
        int idx = tid + it * 256;
        int r = idx >> 4, c = (idx & 15) << 2;
        int gr = n0 + r;
        if (gr < N)
            *(float4*)(y + (size_t)gr * 256 + j0 + c) = *(float4*)(stage + r * 68 + c);
    }
}

// ---------------------------------------------------------------------------
// Kernel 2: warp-specialized persistent edge GEMM (R7-proven protocol,
// rebalanced). 512 threads: warps 0-11 consumers (3m x 4n, each m32n32 over
// M=96 x N=128), warps 12-15 producers (128 threads, 1 thread per edge row).
// K=256 in 8 chunks of 32; h chunk buffers 4-deep.
// D = Ahi*Bhi + Ahi*Blo + Alo*Bhi  (fp32 accum)
// Named barriers (count 512): full[buf]=1+buf, empty[buf]=5+buf, buf=g&3.
// ---------------------------------------------------------------------------
// smem: W2hi [128][264]bf16 (67584), W2lo (67584),
//       4 x h-chunk buf: hi [96 rows][40 bf16] (7680) + lo (7680) = 15360
//       row stride 80 B (5x16 -> ldmatrix 8-row phases conflict-free)
#define SM_WHI 0
#define SM_WLO 67584
#define SM_H   135168
#define HBUF   15360
#define HHALF  7680
#define HSTRIDE 80
#define SMEM_EDGE (135168 + 4 * 15360)   // 196608 B

__global__ __launch_bounds__(512, 1) void edge_mma_kernel(
    const int* __restrict__ edge_index,
    const float* __restrict__ W2, const float* __restrict__ b2,
    float* __restrict__ out, int E)
{
    extern __shared__ __align__(16) char smem[];
    const float* __restrict__ y = g_y;
    const u32 sbase = smem_u32(smem);

    const int tid  = threadIdx.x;
    const int lane = tid & 31;
    const int wid  = tid >> 5;

    // --- one-time: W2 hi/lo split into smem (all threads) ---
    for (int idx = tid; idx < 128 * 256; idx += 512) {
        int n = idx >> 8, k = idx & 255;
        float w = W2[idx];
        __nv_bfloat16 hb = __float2bfloat16(w);
        __nv_bfloat16 lb = __float2bfloat16(w - __bfloat162float(hb));
        u32 byte = (u32)n * 528u + (u32)k * 2u;
        *(__nv_bfloat16*)(smem + SM_WHI + byte) = hb;
        *(__nv_bfloat16*)(smem + SM_WLO + byte) = lb;
    }
    __syncthreads();

    const int ntiles = (E + 95) / 96;

    if (wid < 12) {
        // ===== CONSUMERS: 12 warps, 3m x 4n, each m32 x n32 =====
        const int wm = wid % 3;       // 32-row group (0..2)
        const int wn = wid / 3;       // 32-col group (0..3)

        const u32 aoff = (u32)(lane & 15) * HSTRIDE + (u32)(lane >> 4) * 16u;
        const u32 boff = ((u32)(lane & 7) + (u32)((lane >> 4) & 1) * 8u) * 528u
                       + (u32)((lane >> 3) & 1) * 16u;
        const u32 sa0 = sbase + SM_H + (u32)(wm * 32) * HSTRIDE + aoff;
        const u32 sbH = sbase + SM_WHI + (u32)(wn * 32) * 528u + boff;
        const u32 sbL = sbH + 67584u;

        // bias, pre-scaled
        float bbx[4], bby[4];
        #pragma unroll
        for (int j = 0; j < 4; j++) {
            int col = wn * 32 + j * 8 + (lane & 3) * 2;
            bbx[j] = b2[col] * EPS_VAL;
            bby[j] = b2[col + 1] * EPS_VAL;
        }

        int g = 0;
        for (int t = blockIdx.x; t < ntiles; t += gridDim.x) {
            float acc[2][4][4];
            #pragma unroll
            for (int mt = 0; mt < 2; mt++)
                #pragma unroll
                for (int j = 0; j < 4; j++)
                    #pragma unroll
                    for (int v = 0; v < 4; v++) acc[mt][j][v] = 0.f;

            for (int c = 0; c < 8; c++, g++) {
                const int buf = g & 3;
                BAR_SYNC(1 + buf);
                const u32 saH = sa0 + (u32)buf * HBUF;
                const u32 saL = saH + HHALF;

                #pragma unroll
                for (int ks = 0; ks < 2; ks++) {
                    const u32 ka = (u32)ks * 32u;         // k16 step in h row
                    const u32 kb = (u32)c * 64u + ka;     // k16 step in W2 row
                    u32 aH[2][4], aL[2][4], bH[8], bL[8];
                    ldmx4(aH[0], saH + ka);
                    ldmx4(aH[1], saH + 16u * HSTRIDE + ka);
                    ldmx4(aL[0], saL + ka);
                    ldmx4(aL[1], saL + 16u * HSTRIDE + ka);
                    ldmx4(bH,     sbH + kb);
                    ldmx4(bH + 4, sbH + 16u * 528u + kb);
                    ldmx4(bL,     sbL + kb);
                    ldmx4(bL + 4, sbL + 16u * 528u + kb);
                    #pragma unroll
                    for (int mt = 0; mt < 2; mt++)
                        #pragma unroll
                        for (int j = 0; j < 4; j++) {
                            mma_bf16(acc[mt][j], aH[mt], bH[2*j], bH[2*j+1]);
                            mma_bf16(acc[mt][j], aH[mt], bL[2*j], bL[2*j+1]);
                            mma_bf16(acc[mt][j], aL[mt], bH[2*j], bH[2*j+1]);
                        }
                }
                BAR_ARRIVE(5 + buf);
            }

            // epilogue
            const int t0 = t * 96;
            #pragma unroll
            for (int mt = 0; mt < 2; mt++)
                #pragma unroll
                for (int j = 0; j < 4; j++) {
                    int col = wn * 32 + j * 8 + (lane & 3) * 2;
                    int r0 = t0 + wm * 32 + mt * 16 + (lane >> 2);
                    if (r0 < E) {
                        float2 v;
                        v.x = fmaf(acc[mt][j][0], EPS_VAL, bbx[j]);
                        v.y = fmaf(acc[mt][j][1], EPS_VAL, bby[j]);
                        *(float2*)(out + (size_t)r0 * 128 + col) = v;
                    }
                    int r1 = r0 + 8;
                    if (r1 < E) {
                        float2 v;
                        v.x = fmaf(acc[mt][j][2], EPS_VAL, bbx[j]);
                        v.y = fmaf(acc[mt][j][3], EPS_VAL, bby[j]);
                        *(float2*)(out + (size_t)r1 * 128 + col) = v;
                    }
                }
        }
    } else {
        // ===== PRODUCERS: 4 warps (128 threads), 1 thread per edge row =====
        const int r = tid - 384;          // 0..127; active if r < 96
        const bool act = (r < 96);

        int g = 0;
        for (int t = blockIdx.x; t < ntiles; t += gridDim.x) {
            const int e = t * 96 + r;
            const bool valid = act && (e < E);
            int s = 0, dd = 0;
            if (valid) { s = edge_index[e]; dd = edge_index[E + e]; }
            const float* ys = y + (size_t)s  * 256;
            const float* yd = y + (size_t)dd * 256;
            char* hrow = smem + SM_H + (act ? r : 0) * HSTRIDE;

            for (int c = 0; c < 8; c++, g++) {
                const int buf = g & 3;
                if (g >= 4) BAR_SYNC(5 + buf);

                if (valid) {
                    char* hhi = hrow + buf * HBUF;
                    char* hlo = hhi + HHALF;
                    // process chunk (32 floats) in 2 halves of 16 to cap regs
                    #pragma unroll
                    for (int half = 0; half < 2; half++) {
                        float4 A[4], B[4];
                        #pragma unroll
                        for (int j = 0; j < 4; j++) {
                            A[j] = *(const float4*)(ys + c * 32 + half * 16 + 4 * j);
                            B[j] = *(const float4*)(yd + c * 32 + half * 16 + 4 * j);
                        }
                        u32 hi[8], lo[8];
                        #pragma unroll
                        for (int j = 0; j < 4; j++) {
                            float h0 = fmaxf(A[j].x + B[j].x, 0.f);
                            float h1 = fmaxf(A[j].y + B[j].y, 0.f);
                            float h2 = fmaxf(A[j].z + B[j].z, 0.f);
                            float h3 = fmaxf(A[j].w + B[j].w, 0.f);
                            __nv_bfloat16 p0 = __float2bfloat16(h0), p1 = __float2bfloat16(h1);
                            __nv_bfloat16 p2 = __float2bfloat16(h2), p3 = __float2bfloat16(h3);
                            hi[2*j]   = pack_bf16x2(p0, p1);
                            hi[2*j+1] = pack_bf16x2(p2, p3);
                            lo[2*j]   = pack_bf16x2(__float2bfloat16(h0 - __bfloat162float(p0)),
                                                    __float2bfloat16(h1 - __bfloat162float(p1)));
                            lo[2*j+1] = pack_bf16x2(__float2bfloat16(h2 - __bfloat162float(p2)),
                                                    __float2bfloat16(h3 - __bfloat162float(p3)));
                        }
                        *(uint4*)(hhi + half * 32)      = make_uint4(hi[0], hi[1], hi[2], hi[3]);
                        *(uint4*)(hhi + half * 32 + 16) = make_uint4(hi[4], hi[5], hi[6], hi[7]);
                        *(uint4*)(hlo + half * 32)      = make_uint4(lo[0], lo[1], lo[2], lo[3]);
                        *(uint4*)(hlo + half * 32 + 16) = make_uint4(lo[4], lo[5], lo[6], lo[7]);
                    }
                }
                BAR_ARRIVE(1 + buf);
            }
        }
    }
}

// ---------------------------------------------------------------------------
extern "C" void kernel_launch(void* const* d_in, const int* in_sizes, int n_in,
                              void* d_out, int out_size) {
    const float* x  = (const float*)d_in[0];
    const int*   ei = (const int*)d_in[1];     // int32 [2, E]
    const float* W1 = (const float*)d_in[2];
    const float* b1 = (const float*)d_in[3];
    const float* W2 = (const float*)d_in[4];
    const float* b2 = (const float*)d_in[5];
    float* out = (float*)d_out;

    int N = in_sizes[0] / 128;
    int E = in_sizes[1] / 2;

    const int SMEM1 = 2 * 64 * 132 * sizeof(float);
    cudaFuncSetAttribute(node_proj_kernel,
                         cudaFuncAttributeMaxDynamicSharedMemorySize, SMEM1);
    cudaFuncSetAttribute(edge_mma_kernel,
                         cudaFuncAttributeMaxDynamicSharedMemorySize, SMEM_EDGE);

    dim3 g1((N + 63) / 64, 4);
    node_proj_kernel<<<g1, 256, SMEM1>>>(x, W1, b1, N);

    edge_mma_kernel<<<152, 512, SMEM_EDGE>>>(ei, W2, b2, out, E);
}